// round 5
// baseline (speedup 1.0000x reference)
#include <cuda_runtime.h>
#include <cstdint>
#include <cstddef>

// ---------------------------------------------------------------------------
// ObjectDetection post-process: bbox decode + clip + class argmax + greedy NMS
// (300 picks, IoU 0.5) + gather of boxes/scores/masks.
//
// Shapes (fixed by the problem): N=6000 proposals, C=81 classes,
// masks 14x14x81 = 15876 floats per proposal, PADDING=300 outputs.
// Output buffer layout (flattened tuple): [300*4 boxes][300*81 scores][300*15876 masks]
// ---------------------------------------------------------------------------

#define C_CLS      81
#define PAD        300
#define MASK_ELEMS 15876          // 14*14*81
#define NMS_THRESH 0.5f

#define NT   512                  // threads in the NMS block
#define NPT  12                   // elements per thread
#define NP   (NT * NPT)           // 6144 padded slots (>= N)

__device__ __align__(16) float g_pbox[NP * 4];
__device__ float g_area[NP];
__device__ float g_mscore[NP];
__device__ int   g_pick[PAD];
__device__ float g_vf[PAD];

__device__ __forceinline__ float neg_inf() { return __int_as_float(0xff800000); }

// ---------------------------------------------------------------------------
// Kernel 1: one warp per proposal.
//   - argmax over all C classes (first-index tie-break, like jnp.argmax)
//   - max score over classes [1:]
//   - bbox_transform_inv + clip for ONLY the argmax class (selection commutes)
// ---------------------------------------------------------------------------
__global__ void prep_kernel(const float* __restrict__ metadata,
                            const float* __restrict__ deltas,
                            const float* __restrict__ proposals,
                            const float* __restrict__ scores,
                            int N)
{
    int warp = (blockIdx.x * blockDim.x + threadIdx.x) >> 5;
    int lane = threadIdx.x & 31;
    if (warp >= NP) return;

    if (warp >= N) {            // padding slots: dead entries
        if (lane == 0) {
            reinterpret_cast<float4*>(g_pbox)[warp] = make_float4(0.f, 0.f, 0.f, 0.f);
            g_area[warp]   = 0.f;
            g_mscore[warp] = neg_inf();
        }
        return;
    }

    const float* srow = scores + (size_t)warp * C_CLS;
    float bestv = neg_inf();
    int   besti = 0x7fffffff;
    float mx    = neg_inf();
    for (int c = lane; c < C_CLS; c += 32) {
        float v = __ldg(srow + c);
        if (v > bestv || (v == bestv && c < besti)) { bestv = v; besti = c; }
        if (c >= 1) mx = fmaxf(mx, v);
    }
    #pragma unroll
    for (int off = 16; off; off >>= 1) {
        float ov = __shfl_down_sync(0xffffffffu, bestv, off);
        int   oi = __shfl_down_sync(0xffffffffu, besti, off);
        float om = __shfl_down_sync(0xffffffffu, mx,    off);
        if (ov > bestv || (ov == bestv && oi < besti)) { bestv = ov; besti = oi; }
        mx = fmaxf(mx, om);
    }

    if (lane == 0) {
        float H = metadata[0], W = metadata[1], scale = metadata[2];

        float px1 = __fdiv_rn(proposals[warp * 4 + 0], scale);
        float py1 = __fdiv_rn(proposals[warp * 4 + 1], scale);
        float px2 = __fdiv_rn(proposals[warp * 4 + 2], scale);
        float py2 = __fdiv_rn(proposals[warp * 4 + 3], scale);

        float w  = px2 - px1 + 1.0f;
        float h  = py2 - py1 + 1.0f;
        float cx = px1 + 0.5f * w;
        float cy = py1 + 0.5f * h;

        const float* drow = deltas + (size_t)warp * (4 * C_CLS) + (size_t)besti * 4;
        float dx = drow[0], dy = drow[1], dw = drow[2], dh = drow[3];

        float pcx = dx * w + cx;
        float pcy = dy * h + cy;
        float pw  = expf(dw) * w;
        float ph  = expf(dh) * h;

        float x1 = pcx - 0.5f * pw;
        float y1 = pcy - 0.5f * ph;
        float x2 = pcx + 0.5f * pw;
        float y2 = pcy + 0.5f * ph;

        // clip: x in [0, W-1], y in [0, H-1]
        x1 = fminf(fmaxf(x1, 0.f), W - 1.f);
        y1 = fminf(fmaxf(y1, 0.f), H - 1.f);
        x2 = fminf(fmaxf(x2, 0.f), W - 1.f);
        y2 = fminf(fmaxf(y2, 0.f), H - 1.f);

        reinterpret_cast<float4*>(g_pbox)[warp] = make_float4(x1, y1, x2, y2);
        g_area[warp]   = (x2 - x1 + 1.f) * (y2 - y1 + 1.f);
        g_mscore[warp] = mx;
    }
}

// ---------------------------------------------------------------------------
// Kernel 2: greedy NMS, one persistent block.
// Scores + coords live in registers (NPT per thread); SMEM mirrors coords for
// the pivot-broadcast read. 2 block barriers per iteration.
// ---------------------------------------------------------------------------
__global__ void __launch_bounds__(NT, 1) nms_kernel()
{
    extern __shared__ float sm[];
    float* sx1  = sm;
    float* sy1  = sm + NP;
    float* sx2  = sm + 2 * NP;
    float* sy2  = sm + 3 * NP;
    float* sar  = sm + 4 * NP;
    float* redv = sm + 5 * NP;                 // 32 floats
    int*   redi = (int*)(sm + 5 * NP + 32);    // 32 ints
    float* bc   = sm + 5 * NP + 64;            // bc[0]=val, bc[1]=idx bits

    const int t    = threadIdx.x;
    const int wid  = t >> 5;
    const int lane = t & 31;
    const int nwarp = NT / 32;

    float rs[NPT], rx1[NPT], ry1[NPT], rx2[NPT], ry2[NPT], ra[NPT];
    const float4* pb = reinterpret_cast<const float4*>(g_pbox);

    #pragma unroll
    for (int j = 0; j < NPT; j++) {
        int k = t + j * NT;
        float4 b = pb[k];
        rx1[j] = b.x; ry1[j] = b.y; rx2[j] = b.z; ry2[j] = b.w;
        ra[j]  = g_area[k];
        rs[j]  = g_mscore[k];
        sx1[k] = b.x; sy1[k] = b.y; sx2[k] = b.z; sy2[k] = b.w; sar[k] = ra[j];
    }
    __syncthreads();

    for (int it = 0; it < PAD; it++) {
        // ---- argmax (first-index tie-break) ----
        float bv = neg_inf();
        int   bi = 0x7fffffff;
        #pragma unroll
        for (int j = 0; j < NPT; j++) {
            int k = t + j * NT;
            float v = rs[j];
            if (v > bv || (v == bv && k < bi)) { bv = v; bi = k; }
        }
        #pragma unroll
        for (int off = 16; off; off >>= 1) {
            float ov = __shfl_down_sync(0xffffffffu, bv, off);
            int   oi = __shfl_down_sync(0xffffffffu, bi, off);
            if (ov > bv || (ov == bv && oi < bi)) { bv = ov; bi = oi; }
        }
        if (lane == 0) { redv[wid] = bv; redi[wid] = bi; }
        __syncthreads();

        if (wid == 0) {
            float v2 = (lane < nwarp) ? redv[lane] : neg_inf();
            int   i2 = (lane < nwarp) ? redi[lane] : 0x7fffffff;
            #pragma unroll
            for (int off = 16; off; off >>= 1) {
                float ov = __shfl_down_sync(0xffffffffu, v2, off);
                int   oi = __shfl_down_sync(0xffffffffu, i2, off);
                if (ov > v2 || (ov == v2 && oi < i2)) { v2 = ov; i2 = oi; }
            }
            if (lane == 0) {
                bc[0] = v2;
                ((int*)bc)[1] = i2;
                g_pick[it] = i2;
                g_vf[it]   = (v2 > neg_inf()) ? 1.0f : 0.0f;
            }
        }
        __syncthreads();

        const int   i   = ((int*)bc)[1];
        const float px1 = sx1[i], py1 = sy1[i], px2 = sx2[i], py2 = sy2[i], pa = sar[i];

        // ---- suppress (register-only) ----
        #pragma unroll
        for (int j = 0; j < NPT; j++) {
            int k = t + j * NT;
            float xx1 = fmaxf(px1, rx1[j]);
            float yy1 = fmaxf(py1, ry1[j]);
            float xx2 = fminf(px2, rx2[j]);
            float yy2 = fminf(py2, ry2[j]);
            float iw  = fmaxf(xx2 - xx1 + 1.f, 0.f);
            float ih  = fmaxf(yy2 - yy1 + 1.f, 0.f);
            float inter = iw * ih;
            float iou   = __fdiv_rn(inter, pa + ra[j] - inter);
            if (iou > NMS_THRESH || k == i) rs[j] = neg_inf();
        }
        // no barrier needed here: next argmax reads only own registers; SMEM
        // hazards are covered by the two barriers above (see write/read order).
    }
}

// ---------------------------------------------------------------------------
// Kernel 3: gather. One block per output slot j.
// ---------------------------------------------------------------------------
__global__ void gather_kernel(const float* __restrict__ scores,
                              const float* __restrict__ masks,
                              float* __restrict__ out)
{
    const int j  = blockIdx.x;
    const int i  = g_pick[j];
    const float vf = g_vf[j];
    const int t  = threadIdx.x;

    if (t < 4) out[j * 4 + t] = g_pbox[i * 4 + t] * vf;

    const float* srow = scores + (size_t)i * C_CLS;
    float* os = out + PAD * 4 + (size_t)j * C_CLS;
    for (int c = t; c < C_CLS; c += blockDim.x) os[c] = srow[c] * vf;

    const float4* mrow = reinterpret_cast<const float4*>(masks + (size_t)i * MASK_ELEMS);
    float4* om = reinterpret_cast<float4*>(out + PAD * 4 + PAD * C_CLS + (size_t)j * MASK_ELEMS);
    for (int e = t; e < MASK_ELEMS / 4; e += blockDim.x) {
        float4 v = mrow[e];
        v.x *= vf; v.y *= vf; v.z *= vf; v.w *= vf;
        om[e] = v;
    }
}

// ---------------------------------------------------------------------------
extern "C" void kernel_launch(void* const* d_in, const int* in_sizes, int n_in,
                              void* d_out, int out_size)
{
    (void)n_in; (void)out_size;
    const float* metadata  = (const float*)d_in[0];
    const float* deltas    = (const float*)d_in[1];
    const float* proposals = (const float*)d_in[2];
    const float* scores    = (const float*)d_in[3];
    const float* masks     = (const float*)d_in[4];

    int N = in_sizes[2] / 4;
    if (N > NP) N = NP;

    const size_t smem_bytes = (size_t)(5 * NP + 80) * sizeof(float);   // 123,200 B
    cudaFuncSetAttribute(nms_kernel, cudaFuncAttributeMaxDynamicSharedMemorySize,
                         (int)smem_bytes);

    // one warp per (padded) proposal slot
    const int threads = 256;
    const int blocks  = (NP * 32 + threads - 1) / threads;
    prep_kernel<<<blocks, threads>>>(metadata, deltas, proposals, scores, N);

    nms_kernel<<<1, NT, smem_bytes>>>();

    gather_kernel<<<PAD, 256>>>(scores, masks, (float*)d_out);
}

// round 8
// speedup vs baseline: 5.4759x; 5.4759x over previous
#include <cuda_runtime.h>
#include <cstdint>
#include <cstddef>

// ---------------------------------------------------------------------------
// ObjectDetection post-process: bbox decode + clip + class argmax + greedy NMS
// (300 picks, IoU 0.5) + gather of boxes/scores/masks.
//
// N=6000 proposals, C=81 classes, masks 14x14x81=15876 floats, PADDING=300.
// Output layout: [300*4 boxes][300*81 scores][300*15876 masks]
// ---------------------------------------------------------------------------

#define C_CLS      81
#define PAD        300
#define MASK_ELEMS 15876          // 14*14*81

#define NT    512                 // threads in the NMS block
#define NPT   12                  // elements per thread
#define NP    (NT * NPT)          // 6144 padded slots (>= N)
#define NWARP (NT / 32)

__device__ __align__(16) float g_pbox[NP * 4];
__device__ float g_area[NP];
__device__ float g_mscore[NP];
__device__ int   g_pick[PAD];
__device__ float g_vf[PAD];

__device__ __forceinline__ float neg_inf() { return __int_as_float(0xff800000); }

// ---------------------------------------------------------------------------
// Kernel 1: one warp per proposal (arithmetic is pick-determining; unchanged
// from the passing round-4 version).
// ---------------------------------------------------------------------------
__global__ void prep_kernel(const float* __restrict__ metadata,
                            const float* __restrict__ deltas,
                            const float* __restrict__ proposals,
                            const float* __restrict__ scores,
                            int N)
{
    int warp = (blockIdx.x * blockDim.x + threadIdx.x) >> 5;
    int lane = threadIdx.x & 31;
    if (warp >= NP) return;

    if (warp >= N) {            // padding slots: dead entries
        if (lane == 0) {
            reinterpret_cast<float4*>(g_pbox)[warp] = make_float4(0.f, 0.f, 0.f, 0.f);
            g_area[warp]   = 0.f;
            g_mscore[warp] = neg_inf();
        }
        return;
    }

    const float* srow = scores + (size_t)warp * C_CLS;
    float bestv = neg_inf();
    int   besti = 0x7fffffff;
    float mx    = neg_inf();
    for (int c = lane; c < C_CLS; c += 32) {
        float v = __ldg(srow + c);
        if (v > bestv || (v == bestv && c < besti)) { bestv = v; besti = c; }
        if (c >= 1) mx = fmaxf(mx, v);
    }
    #pragma unroll
    for (int off = 16; off; off >>= 1) {
        float ov = __shfl_down_sync(0xffffffffu, bestv, off);
        int   oi = __shfl_down_sync(0xffffffffu, besti, off);
        float om = __shfl_down_sync(0xffffffffu, mx,    off);
        if (ov > bestv || (ov == bestv && oi < besti)) { bestv = ov; besti = oi; }
        mx = fmaxf(mx, om);
    }

    if (lane == 0) {
        float H = metadata[0], W = metadata[1], scale = metadata[2];

        float px1 = __fdiv_rn(proposals[warp * 4 + 0], scale);
        float py1 = __fdiv_rn(proposals[warp * 4 + 1], scale);
        float px2 = __fdiv_rn(proposals[warp * 4 + 2], scale);
        float py2 = __fdiv_rn(proposals[warp * 4 + 3], scale);

        float w  = px2 - px1 + 1.0f;
        float h  = py2 - py1 + 1.0f;
        float cx = px1 + 0.5f * w;
        float cy = py1 + 0.5f * h;

        const float* drow = deltas + (size_t)warp * (4 * C_CLS) + (size_t)besti * 4;
        float dx = drow[0], dy = drow[1], dw = drow[2], dh = drow[3];

        float pcx = dx * w + cx;
        float pcy = dy * h + cy;
        float pw  = expf(dw) * w;
        float ph  = expf(dh) * h;

        float x1 = pcx - 0.5f * pw;
        float y1 = pcy - 0.5f * ph;
        float x2 = pcx + 0.5f * pw;
        float y2 = pcy + 0.5f * ph;

        x1 = fminf(fmaxf(x1, 0.f), W - 1.f);
        y1 = fminf(fmaxf(y1, 0.f), H - 1.f);
        x2 = fminf(fmaxf(x2, 0.f), W - 1.f);
        y2 = fminf(fmaxf(y2, 0.f), H - 1.f);

        reinterpret_cast<float4*>(g_pbox)[warp] = make_float4(x1, y1, x2, y2);
        g_area[warp]   = (x2 - x1 + 1.f) * (y2 - y1 + 1.f);
        g_mscore[warp] = mx;
    }
}

// ---------------------------------------------------------------------------
// Kernel 2: greedy NMS, one persistent block, ONE barrier per iteration.
//  - division-free suppression: iou > 0.5  <=>  2*inter > union (exact; U>0
//    guaranteed since clipping cannot invert a box -> all areas >= 1)
//  - suppress + next local argmax fused in one register pass
//  - (value,index) packed into u64 key; stage-2 reduce done redundantly by
//    every warp from a parity-double-buffered SMEM array (no 2nd barrier)
//  - FIX vs round 5: all 32 lanes mirror the 16 partials via (lane & 15)
//    before the 8/4/2/1 butterfly, so every lane converges to the true max.
// ---------------------------------------------------------------------------
__global__ void __launch_bounds__(NT, 1) nms_kernel()
{
    extern __shared__ float sm[];
    float4* sbox = reinterpret_cast<float4*>(sm);                    // NP float4
    float*  sar  = sm + NP * 4;                                      // NP floats
    unsigned long long* redk =
        reinterpret_cast<unsigned long long*>(sm + NP * 5);          // 2*NWARP keys

    const int t    = threadIdx.x;
    const int wid  = t >> 5;
    const int lane = t & 31;

    float rs[NPT], rx1[NPT], ry1[NPT], rx2[NPT], ry2[NPT], ra[NPT];
    const float4* pb = reinterpret_cast<const float4*>(g_pbox);

    #pragma unroll
    for (int j = 0; j < NPT; j++) {
        int k = t + j * NT;
        float4 b = pb[k];
        rx1[j] = b.x; ry1[j] = b.y; rx2[j] = b.z; ry2[j] = b.w;
        ra[j]  = g_area[k];
        rs[j]  = g_mscore[k];
        sbox[k] = b;
        sar[k]  = ra[j];
    }

    // initial thread-local argmax (strict > keeps first index; k ascends with j)
    float bv = neg_inf();
    int   bj = 0;
    #pragma unroll
    for (int j = 0; j < NPT; j++)
        if (rs[j] > bv) { bv = rs[j]; bj = j; }

    __syncthreads();   // sbox/sar visible to all

    for (int it = 0; it < PAD; it++) {
        // ---- pack (score, index) into a monotone u64 key ----
        int bi = t + bj * NT;
        int fb = __float_as_int(bv);
        unsigned mono = (unsigned)fb ^ (unsigned)((fb >> 31) | 0x80000000);
        unsigned long long key =
            ((unsigned long long)mono << 13) | (unsigned)(NP - 1 - bi);

        // ---- warp reduce (max) ----
        #pragma unroll
        for (int off = 16; off; off >>= 1) {
            unsigned long long o = __shfl_xor_sync(0xffffffffu, key, off);
            if (o > key) key = o;
        }
        if (lane == 0) redk[(it & 1) * NWARP + wid] = key;
        __syncthreads();

        // ---- stage 2: every warp redundantly reduces the 16 partials ----
        // Both 16-lane halves load the same mirrored data (lane & 15), so the
        // 8/4/2/1 butterfly converges ALL 32 lanes to the block-wide max.
        unsigned long long k2 = redk[(it & 1) * NWARP + (lane & 15)];
        #pragma unroll
        for (int off = 8; off; off >>= 1) {
            unsigned long long o = __shfl_xor_sync(0xffffffffu, k2, off);
            if (o > k2) k2 = o;
        }
        int i = NP - 1 - (int)(k2 & 0x1FFFull);
        if (t == 0) {
            g_pick[it] = i;
            // valid <=> picked score > -inf  <=> mono(score) > mono(-inf)=0x007FFFFF
            g_vf[it] = ((k2 >> 13) > 0x007FFFFFull) ? 1.0f : 0.0f;
        }

        float4 pbx = sbox[i];
        float  pa  = sar[i];

        // ---- fused suppress + next local argmax (register-only) ----
        bv = neg_inf(); bj = 0;
        #pragma unroll
        for (int j = 0; j < NPT; j++) {
            float xx1 = fmaxf(pbx.x, rx1[j]);
            float yy1 = fmaxf(pbx.y, ry1[j]);
            float xx2 = fminf(pbx.z, rx2[j]);
            float yy2 = fminf(pbx.w, ry2[j]);
            float iw  = fmaxf((xx2 - xx1) + 1.0f, 0.0f);
            float ih  = fmaxf((yy2 - yy1) + 1.0f, 0.0f);
            float inter = __fmul_rn(iw, ih);                       // no contraction
            float U     = __fadd_rn(__fadd_rn(pa, ra[j]), -inter); // areas[i]+areas-inter
            float lhs   = __fadd_rn(inter, inter);                 // exact 2*inter
            // lhs > U  <=>  fdiv_rn(inter,U) > 0.5 (exact, U>0);
            // self (k==i): inter==pa==U bitwise -> 2pa > pa -> suppressed
            float v = (lhs > U) ? neg_inf() : rs[j];
            rs[j] = v;
            if (v > bv) { bv = v; bj = j; }
        }
    }
}

// ---------------------------------------------------------------------------
// Kernel 3: gather. One block per output slot j.
// ---------------------------------------------------------------------------
__global__ void gather_kernel(const float* __restrict__ scores,
                              const float* __restrict__ masks,
                              float* __restrict__ out)
{
    const int j  = blockIdx.x;
    const int i  = g_pick[j];
    const float vf = g_vf[j];
    const int t  = threadIdx.x;

    if (t < 4) out[j * 4 + t] = g_pbox[i * 4 + t] * vf;

    const float* srow = scores + (size_t)i * C_CLS;
    float* os = out + PAD * 4 + (size_t)j * C_CLS;
    for (int c = t; c < C_CLS; c += blockDim.x) os[c] = srow[c] * vf;

    const float4* mrow = reinterpret_cast<const float4*>(masks + (size_t)i * MASK_ELEMS);
    float4* om = reinterpret_cast<float4*>(out + PAD * 4 + PAD * C_CLS + (size_t)j * MASK_ELEMS);
    for (int e = t; e < MASK_ELEMS / 4; e += blockDim.x) {
        float4 v = mrow[e];
        v.x *= vf; v.y *= vf; v.z *= vf; v.w *= vf;
        om[e] = v;
    }
}

// ---------------------------------------------------------------------------
extern "C" void kernel_launch(void* const* d_in, const int* in_sizes, int n_in,
                              void* d_out, int out_size)
{
    (void)n_in; (void)out_size;
    const float* metadata  = (const float*)d_in[0];
    const float* deltas    = (const float*)d_in[1];
    const float* proposals = (const float*)d_in[2];
    const float* scores    = (const float*)d_in[3];
    const float* masks     = (const float*)d_in[4];

    int N = in_sizes[2] / 4;
    if (N > NP) N = NP;

    // float4 boxes (NP*16B) + areas (NP*4B) + 2*NWARP u64 keys
    const size_t smem_bytes = (size_t)NP * 5 * sizeof(float)
                            + (size_t)2 * NWARP * sizeof(unsigned long long);
    cudaFuncSetAttribute(nms_kernel, cudaFuncAttributeMaxDynamicSharedMemorySize,
                         (int)smem_bytes);

    const int threads = 256;
    const int blocks  = (NP * 32 + threads - 1) / threads;
    prep_kernel<<<blocks, threads>>>(metadata, deltas, proposals, scores, N);

    nms_kernel<<<1, NT, smem_bytes>>>();

    gather_kernel<<<PAD, 512>>>(scores, masks, (float*)d_out);
}

// round 11
// speedup vs baseline: 8.3941x; 1.5329x over previous
#include <cuda_runtime.h>
#include <cstdint>
#include <cstddef>

// ---------------------------------------------------------------------------
// ObjectDetection post-process, sorted-scan NMS formulation:
//   prep   : decode/clip argmax-class box, per-box NMS score, sort key
//   sort   : bitonic sort of (score,index) keys, build sorted box arrays
//   matrix : all-pairs suppression bitmask over sorted order (full chip)
//   scan   : single-warp ordered walk -> 300 picks
//   gather : emit boxes/scores/masks
// Greedy argmax-NMS == sorted-order scan; every FP comparison is kept
// bit-identical to the reference (2*inter > U  <=>  fdiv_rn(inter,U) > 0.5).
// ---------------------------------------------------------------------------

#define C_CLS      81
#define PAD        300
#define MASK_ELEMS 15876          // 14*14*81

#define NP     6144               // padded proposal slots (>= N=6000), 96*64
#define NWORD  96                 // NP / 64
#define NSORT  8192               // pow2 >= NP for bitonic
#define NT_S   512                // sort threads

__device__ __align__(16) float g_pbox[NP * 4];
__device__ float g_area[NP];
__device__ unsigned long long g_key[NP];      // unsorted keys
__device__ unsigned long long g_skey[NP];     // sorted keys
__device__ __align__(16) float g_sbox[NP * 4];// boxes in sorted order
__device__ float g_sar[NP];                   // areas in sorted order
__device__ unsigned long long g_mask[(size_t)NP * NWORD];  // 4.7MB suppression matrix
__device__ int g_pickpos[PAD];                // picked sorted positions

__device__ __forceinline__ float neg_inf() { return __int_as_float(0xff800000); }

// ---------------------------------------------------------------------------
// Kernel 1: one warp per proposal. Decode + clip + argmax class + key build.
// ---------------------------------------------------------------------------
__global__ void prep_kernel(const float* __restrict__ metadata,
                            const float* __restrict__ deltas,
                            const float* __restrict__ proposals,
                            const float* __restrict__ scores,
                            int N)
{
    int warp = (blockIdx.x * blockDim.x + threadIdx.x) >> 5;
    int lane = threadIdx.x & 31;
    if (warp >= NP) return;

    if (warp >= N) {            // padding slots: dead entries, -inf keys
        if (lane == 0) {
            reinterpret_cast<float4*>(g_pbox)[warp] = make_float4(0.f, 0.f, 0.f, 0.f);
            g_area[warp] = 0.f;
            // mono(-inf) = 0x007FFFFF
            g_key[warp] = (0x007FFFFFull << 13) | (unsigned)(NP - 1 - warp);
        }
        return;
    }

    const float* srow = scores + (size_t)warp * C_CLS;
    float bestv = neg_inf();
    int   besti = 0x7fffffff;
    float mx    = neg_inf();
    for (int c = lane; c < C_CLS; c += 32) {
        float v = __ldg(srow + c);
        if (v > bestv || (v == bestv && c < besti)) { bestv = v; besti = c; }
        if (c >= 1) mx = fmaxf(mx, v);
    }
    #pragma unroll
    for (int off = 16; off; off >>= 1) {
        float ov = __shfl_down_sync(0xffffffffu, bestv, off);
        int   oi = __shfl_down_sync(0xffffffffu, besti, off);
        float om = __shfl_down_sync(0xffffffffu, mx,    off);
        if (ov > bestv || (ov == bestv && oi < besti)) { bestv = ov; besti = oi; }
        mx = fmaxf(mx, om);
    }

    if (lane == 0) {
        float H = metadata[0], W = metadata[1], scale = metadata[2];

        float px1 = __fdiv_rn(proposals[warp * 4 + 0], scale);
        float py1 = __fdiv_rn(proposals[warp * 4 + 1], scale);
        float px2 = __fdiv_rn(proposals[warp * 4 + 2], scale);
        float py2 = __fdiv_rn(proposals[warp * 4 + 3], scale);

        float w  = px2 - px1 + 1.0f;
        float h  = py2 - py1 + 1.0f;
        float cx = px1 + 0.5f * w;
        float cy = py1 + 0.5f * h;

        const float* drow = deltas + (size_t)warp * (4 * C_CLS) + (size_t)besti * 4;
        float dx = drow[0], dy = drow[1], dw = drow[2], dh = drow[3];

        float pcx = dx * w + cx;
        float pcy = dy * h + cy;
        float pw  = expf(dw) * w;
        float ph  = expf(dh) * h;

        float x1 = pcx - 0.5f * pw;
        float y1 = pcy - 0.5f * ph;
        float x2 = pcx + 0.5f * pw;
        float y2 = pcy + 0.5f * ph;

        x1 = fminf(fmaxf(x1, 0.f), W - 1.f);
        y1 = fminf(fmaxf(y1, 0.f), H - 1.f);
        x2 = fminf(fmaxf(x2, 0.f), W - 1.f);
        y2 = fminf(fmaxf(y2, 0.f), H - 1.f);

        reinterpret_cast<float4*>(g_pbox)[warp] = make_float4(x1, y1, x2, y2);
        g_area[warp] = (x2 - x1 + 1.f) * (y2 - y1 + 1.f);

        // monotone key: (mono(score) << 13) | (NP-1-k)  -> desc sort == argmax order
        int mb = __float_as_int(mx);
        unsigned mono = (unsigned)mb ^ (unsigned)((mb >> 31) | 0x80000000);
        g_key[warp] = ((unsigned long long)mono << 13) | (unsigned)(NP - 1 - warp);
    }
}

// ---------------------------------------------------------------------------
// Kernel 2: single-block bitonic sort (descending) of NSORT u64 keys in smem,
// then emit sorted keys + sorted box/area arrays.
// ---------------------------------------------------------------------------
__global__ void __launch_bounds__(NT_S, 1) sort_kernel()
{
    extern __shared__ unsigned long long s[];
    const int tid = threadIdx.x;

    for (int i = tid; i < NSORT; i += NT_S)
        s[i] = (i < NP) ? g_key[i] : 0ull;      // fillers sort last (desc)
    __syncthreads();

    for (int len = 2; len <= NSORT; len <<= 1) {
        for (int inc = len >> 1; inc > 0; inc >>= 1) {
            for (int ii = tid; ii < NSORT / 2; ii += NT_S) {
                int low = ii & (inc - 1);
                int i   = ((ii ^ low) << 1) | low;     // pair base (inc-bit clear)
                int j   = i + inc;
                unsigned long long a = s[i], b = s[j];
                bool up = ((i & len) == 0);
                bool sw = up ? (a < b) : (a > b);      // descending network
                if (sw) { s[i] = b; s[j] = a; }
            }
            __syncthreads();
        }
    }

    // epilogue: sorted arrays
    for (int pos = tid; pos < NP; pos += NT_S) {
        unsigned long long key = s[pos];
        int k = NP - 1 - (int)(key & 0x1FFFull);
        g_skey[pos] = key;
        reinterpret_cast<float4*>(g_sbox)[pos] =
            reinterpret_cast<const float4*>(g_pbox)[k];
        g_sar[pos] = g_area[k];
    }
}

// ---------------------------------------------------------------------------
// Kernel 3: suppression matrix over sorted order. One warp per row r;
// each word w (>= r/64) packs [IoU(r,c) > 0.5] for c in [64w, 64w+64), c > r.
// Lower-triangle words are left unwritten: the scan ANDNs them only against
// positions already dead (< pick position), so garbage is harmless AND
// replay-deterministic (never written by anyone).
// ---------------------------------------------------------------------------
__device__ __forceinline__ bool sup_test(float4 p, float pa, float4 b, float ba)
{
    float xx1 = fmaxf(p.x, b.x);
    float yy1 = fmaxf(p.y, b.y);
    float xx2 = fminf(p.z, b.z);
    float yy2 = fminf(p.w, b.w);
    float iw  = fmaxf((xx2 - xx1) + 1.0f, 0.0f);
    float ih  = fmaxf((yy2 - yy1) + 1.0f, 0.0f);
    float inter = __fmul_rn(iw, ih);
    float U     = __fadd_rn(__fadd_rn(pa, ba), -inter);
    // exact: 2*inter > U  <=>  fdiv_rn(inter, U) > 0.5   (U > 0 here)
    return __fadd_rn(inter, inter) > U;
}

__global__ void matrix_kernel()
{
    int r    = (blockIdx.x * blockDim.x + threadIdx.x) >> 5;
    int lane = threadIdx.x & 31;
    if (r >= NP) return;

    const float4 pb = reinterpret_cast<const float4*>(g_sbox)[r];
    const float  pa = g_sar[r];

    for (int w = r >> 6; w < NWORD; w++) {
        int c0 = (w << 6) + lane;
        int c1 = c0 + 32;
        float4 b0 = reinterpret_cast<const float4*>(g_sbox)[c0];
        float  a0 = g_sar[c0];
        float4 b1 = reinterpret_cast<const float4*>(g_sbox)[c1];
        float  a1 = g_sar[c1];
        bool s0 = (c0 > r) && sup_test(pb, pa, b0, a0);
        bool s1 = (c1 > r) && sup_test(pb, pa, b1, a1);
        unsigned m0 = __ballot_sync(0xffffffffu, s0);
        unsigned m1 = __ballot_sync(0xffffffffu, s1);
        if (lane == 0)
            g_mask[(size_t)r * NWORD + w] =
                (unsigned long long)m0 | ((unsigned long long)m1 << 32);
    }
}

// ---------------------------------------------------------------------------
// Kernel 4: single-warp ordered scan. Alive bitmask in registers
// (lane owns words 3*lane..3*lane+2). Rows prefetched 8 positions ahead
// into a register ring so pick-apply never waits on L2.
// ---------------------------------------------------------------------------
__global__ void scan_kernel()
{
    const int lane = threadIdx.x;

    unsigned long long a0 = ~0ull, a1 = ~0ull, a2 = ~0ull;   // all 6144 alive
    unsigned long long B0[8], B1[8], B2[8];

    #pragma unroll
    for (int s = 0; s < 8; s++) {
        const unsigned long long* row = g_mask + (size_t)s * NWORD + lane * 3;
        B0[s] = row[0]; B1[s] = row[1]; B2[s] = row[2];
    }

    int picks = 0;
    for (int q = 0; q < NP && picks < PAD; q += 8) {
        #pragma unroll
        for (int s = 0; s < 8; s++) {
            int pos = q + s;
            if (picks < PAD) {
                int w  = pos >> 6;
                int ow = w / 3;
                int m  = w - ow * 3;
                unsigned long long wv = (m == 0) ? a0 : (m == 1) ? a1 : a2;
                wv = __shfl_sync(0xffffffffu, wv, ow);
                if ((wv >> (pos & 63)) & 1ull) {
                    // pick: suppress later boxes, clear own bit
                    a0 &= ~B0[s]; a1 &= ~B1[s]; a2 &= ~B2[s];
                    if (lane == ow) {
                        unsigned long long bm = ~(1ull << (pos & 63));
                        if (m == 0) a0 &= bm; else if (m == 1) a1 &= bm; else a2 &= bm;
                    }
                    if (lane == 0) g_pickpos[picks] = pos;
                    picks++;
                }
            }
            int nidx = q + s + 8;
            if (nidx > NP - 1) nidx = NP - 1;
            const unsigned long long* row = g_mask + (size_t)nidx * NWORD + lane * 3;
            B0[s] = row[0]; B1[s] = row[1]; B2[s] = row[2];
        }
    }
    // exhausted: remaining picks -> last position (always a -inf pad => vf=0)
    if (lane == 0)
        for (; picks < PAD; picks++) g_pickpos[picks] = NP - 1;
}

// ---------------------------------------------------------------------------
// Kernel 5: gather. One block per output slot j; translate sorted pos ->
// original index + validity via the sorted key.
// ---------------------------------------------------------------------------
__global__ void gather_kernel(const float* __restrict__ scores,
                              const float* __restrict__ masks,
                              float* __restrict__ out)
{
    const int j   = blockIdx.x;
    const int pos = g_pickpos[j];
    const unsigned long long key = g_skey[pos];
    const int   i  = NP - 1 - (int)(key & 0x1FFFull);
    const float vf = ((key >> 13) > 0x007FFFFFull) ? 1.0f : 0.0f;
    const int t = threadIdx.x;

    if (t < 4) out[j * 4 + t] = g_pbox[i * 4 + t] * vf;

    const float* srow = scores + (size_t)i * C_CLS;
    float* os = out + PAD * 4 + (size_t)j * C_CLS;
    for (int c = t; c < C_CLS; c += blockDim.x) os[c] = srow[c] * vf;

    const float4* mrow = reinterpret_cast<const float4*>(masks + (size_t)i * MASK_ELEMS);
    float4* om = reinterpret_cast<float4*>(out + PAD * 4 + PAD * C_CLS + (size_t)j * MASK_ELEMS);
    for (int e = t; e < MASK_ELEMS / 4; e += blockDim.x) {
        float4 v = mrow[e];
        v.x *= vf; v.y *= vf; v.z *= vf; v.w *= vf;
        om[e] = v;
    }
}

// ---------------------------------------------------------------------------
extern "C" void kernel_launch(void* const* d_in, const int* in_sizes, int n_in,
                              void* d_out, int out_size)
{
    (void)n_in; (void)out_size;
    const float* metadata  = (const float*)d_in[0];
    const float* deltas    = (const float*)d_in[1];
    const float* proposals = (const float*)d_in[2];
    const float* scores    = (const float*)d_in[3];
    const float* masks     = (const float*)d_in[4];

    int N = in_sizes[2] / 4;
    if (N > NP) N = NP;

    const size_t sort_smem = (size_t)NSORT * sizeof(unsigned long long);  // 64KB
    cudaFuncSetAttribute(sort_kernel, cudaFuncAttributeMaxDynamicSharedMemorySize,
                         (int)sort_smem);

    // 1) prep: one warp per slot
    {
        const int threads = 256;
        const int blocks  = (NP * 32 + threads - 1) / threads;
        prep_kernel<<<blocks, threads>>>(metadata, deltas, proposals, scores, N);
    }
    // 2) sort
    sort_kernel<<<1, NT_S, sort_smem>>>();
    // 3) suppression matrix: one warp per sorted row
    {
        const int threads = 256;                       // 8 warps/block
        const int blocks  = NP / 8;                    // 768
        matrix_kernel<<<blocks, threads>>>();
    }
    // 4) scan: one warp
    scan_kernel<<<1, 32>>>();
    // 5) gather
    gather_kernel<<<PAD, 512>>>(scores, masks, (float*)d_out);
}

// round 12
// speedup vs baseline: 10.5139x; 1.2525x over previous
#include <cuda_runtime.h>
#include <cstdint>
#include <cstddef>

// ---------------------------------------------------------------------------
// ObjectDetection post-process, sorted-scan NMS formulation:
//   prep   : decode/clip argmax-class box, per-box NMS score, sort key
//   sort   : register-blocked bitonic sort of (score,index) keys
//   matrix : all-pairs suppression bitmask over sorted order (full chip)
//   scan   : chunked pick-skip scan with cp.async row staging
//   gather : emit boxes/scores/masks
// ---------------------------------------------------------------------------

#define C_CLS      81
#define PAD        300
#define MASK_ELEMS 15876          // 14*14*81

#define NP     6144               // padded proposal slots (>= N=6000), 96*64
#define NWORD  96                 // NP / 64
#define NCHUNK 96                 // NP / 64
#define NSORT  8192               // pow2 >= NP for bitonic
#define NT_S   512                // sort threads
#define NT_SC  512                // scan threads

__device__ __align__(16) float g_pbox[NP * 4];
__device__ float g_area[NP];
__device__ __align__(16) unsigned long long g_key[NP];     // unsorted keys
__device__ __align__(16) unsigned long long g_skey[NP];    // sorted keys
__device__ __align__(16) float g_sbox[NP * 4];             // boxes, sorted order
__device__ float g_sar[NP];                                // areas, sorted order
__device__ __align__(16) unsigned long long g_mask[(size_t)NP * NWORD]; // 4.7MB
__device__ int g_pickpos[PAD];                             // picked sorted positions

__device__ __forceinline__ float neg_inf() { return __int_as_float(0xff800000); }

// ---------------------------------------------------------------------------
// Kernel 1: one warp per proposal. Decode + clip + argmax class + key build.
// (pick-determining arithmetic — unchanged from the passing version)
// ---------------------------------------------------------------------------
__global__ void prep_kernel(const float* __restrict__ metadata,
                            const float* __restrict__ deltas,
                            const float* __restrict__ proposals,
                            const float* __restrict__ scores,
                            int N)
{
    int warp = (blockIdx.x * blockDim.x + threadIdx.x) >> 5;
    int lane = threadIdx.x & 31;
    if (warp >= NP) return;

    if (warp >= N) {            // padding slots: dead entries, -inf keys
        if (lane == 0) {
            reinterpret_cast<float4*>(g_pbox)[warp] = make_float4(0.f, 0.f, 0.f, 0.f);
            g_area[warp] = 0.f;
            g_key[warp] = (0x007FFFFFull << 13) | (unsigned)(NP - 1 - warp);
        }
        return;
    }

    const float* srow = scores + (size_t)warp * C_CLS;
    float bestv = neg_inf();
    int   besti = 0x7fffffff;
    float mx    = neg_inf();
    for (int c = lane; c < C_CLS; c += 32) {
        float v = __ldg(srow + c);
        if (v > bestv || (v == bestv && c < besti)) { bestv = v; besti = c; }
        if (c >= 1) mx = fmaxf(mx, v);
    }
    #pragma unroll
    for (int off = 16; off; off >>= 1) {
        float ov = __shfl_down_sync(0xffffffffu, bestv, off);
        int   oi = __shfl_down_sync(0xffffffffu, besti, off);
        float om = __shfl_down_sync(0xffffffffu, mx,    off);
        if (ov > bestv || (ov == bestv && oi < besti)) { bestv = ov; besti = oi; }
        mx = fmaxf(mx, om);
    }

    if (lane == 0) {
        float H = metadata[0], W = metadata[1], scale = metadata[2];

        float px1 = __fdiv_rn(proposals[warp * 4 + 0], scale);
        float py1 = __fdiv_rn(proposals[warp * 4 + 1], scale);
        float px2 = __fdiv_rn(proposals[warp * 4 + 2], scale);
        float py2 = __fdiv_rn(proposals[warp * 4 + 3], scale);

        float w  = px2 - px1 + 1.0f;
        float h  = py2 - py1 + 1.0f;
        float cx = px1 + 0.5f * w;
        float cy = py1 + 0.5f * h;

        const float* drow = deltas + (size_t)warp * (4 * C_CLS) + (size_t)besti * 4;
        float dx = drow[0], dy = drow[1], dw = drow[2], dh = drow[3];

        float pcx = dx * w + cx;
        float pcy = dy * h + cy;
        float pw  = expf(dw) * w;
        float ph  = expf(dh) * h;

        float x1 = pcx - 0.5f * pw;
        float y1 = pcy - 0.5f * ph;
        float x2 = pcx + 0.5f * pw;
        float y2 = pcy + 0.5f * ph;

        x1 = fminf(fmaxf(x1, 0.f), W - 1.f);
        y1 = fminf(fmaxf(y1, 0.f), H - 1.f);
        x2 = fminf(fmaxf(x2, 0.f), W - 1.f);
        y2 = fminf(fmaxf(y2, 0.f), H - 1.f);

        reinterpret_cast<float4*>(g_pbox)[warp] = make_float4(x1, y1, x2, y2);
        g_area[warp] = (x2 - x1 + 1.f) * (y2 - y1 + 1.f);

        int mb = __float_as_int(mx);
        unsigned mono = (unsigned)mb ^ (unsigned)((mb >> 31) | 0x80000000);
        g_key[warp] = ((unsigned long long)mono << 13) | (unsigned)(NP - 1 - warp);
    }
}

// ---------------------------------------------------------------------------
// Kernel 2: register-blocked bitonic sort (descending).
// Identical comparator network to the previously-passing sort, re-scheduled:
// all inc<=8 steps (and the whole len<=16 prefix) run in registers; smem steps
// use an XOR swizzle so the 16-contiguous-per-thread accesses are conflict-free.
// ---------------------------------------------------------------------------
#define SW(i) ((i) ^ (((i) >> 4) & 15))

__device__ __forceinline__ void cas_d(unsigned long long& a, unsigned long long& b,
                                      bool desc)
{
    unsigned long long mx = (a > b) ? a : b;
    unsigned long long mn = (a > b) ? b : a;
    a = desc ? mx : mn;
    b = desc ? mn : mx;
}

__device__ __forceinline__ void sort16(unsigned long long v[16], bool desc16)
{
    // len = 2, 4, 8 phases: direction (i&len)==0 with i=base+j == (j&len)==0
    #pragma unroll
    for (int len = 2; len <= 8; len <<= 1) {
        #pragma unroll
        for (int inc = len >> 1; inc >= 1; inc >>= 1) {
            #pragma unroll
            for (int j = 0; j < 16; j++)
                if ((j & inc) == 0)
                    cas_d(v[j], v[j | inc], ((j & len) == 0));
        }
    }
    // len = 16 phase: direction constant per 16-block
    #pragma unroll
    for (int inc = 8; inc >= 1; inc >>= 1) {
        #pragma unroll
        for (int j = 0; j < 16; j++)
            if ((j & inc) == 0)
                cas_d(v[j], v[j | inc], desc16);
    }
}

__device__ __forceinline__ void merge16(unsigned long long v[16], bool desc)
{
    #pragma unroll
    for (int inc = 8; inc >= 1; inc >>= 1) {
        #pragma unroll
        for (int j = 0; j < 16; j++)
            if ((j & inc) == 0)
                cas_d(v[j], v[j | inc], desc);
    }
}

__global__ void __launch_bounds__(NT_S, 1) sort_kernel()
{
    extern __shared__ __align__(16) unsigned long long s[];
    const int t    = threadIdx.x;
    const int base = t * 16;

    unsigned long long v[16];
    #pragma unroll
    for (int j = 0; j < 16; j++) {
        int i = base + j;
        v[j] = (i < NP) ? g_key[i] : 0ull;       // fillers sort last (desc)
    }
    sort16(v, ((base & 16) == 0));
    #pragma unroll
    for (int j = 0; j < 16; j++) s[SW(base + j)] = v[j];
    __syncthreads();

    for (int len = 32; len <= NSORT; len <<= 1) {
        for (int inc = len >> 1; inc >= 16; inc >>= 1) {
            for (int ii = t; ii < NSORT / 2; ii += NT_S) {
                int low = ii & (inc - 1);
                int i   = ((ii ^ low) << 1) | low;
                int j   = i + inc;
                unsigned long long a = s[SW(i)], b = s[SW(j)];
                bool up = ((i & len) == 0);
                bool sw_ = up ? (a < b) : (a > b);   // descending network
                if (sw_) { s[SW(i)] = b; s[SW(j)] = a; }
            }
            __syncthreads();
        }
        // register-local merge for inc = 8..1 (direction constant per block)
        #pragma unroll
        for (int j = 0; j < 16; j++) v[j] = s[SW(base + j)];
        merge16(v, ((base & len) == 0));
        #pragma unroll
        for (int j = 0; j < 16; j++) s[SW(base + j)] = v[j];
        __syncthreads();
    }

    // epilogue: sorted keys + sorted box/area arrays
    for (int pos = t; pos < NP; pos += NT_S) {
        unsigned long long key = s[SW(pos)];
        int k = NP - 1 - (int)(key & 0x1FFFull);
        g_skey[pos] = key;
        reinterpret_cast<float4*>(g_sbox)[pos] =
            reinterpret_cast<const float4*>(g_pbox)[k];
        g_sar[pos] = g_area[k];
    }
}

// ---------------------------------------------------------------------------
// Kernel 3: suppression matrix over sorted order. One warp per row r;
// word w (>= r/64) packs [IoU(r,c) > 0.5] for c in [64w,64w+64), c > r.
// Lower-triangle words are left unwritten (provably harmless: the scan's
// ANDN can only clear bits that are already zero there).
// ---------------------------------------------------------------------------
__device__ __forceinline__ bool sup_test(float4 p, float pa, float4 b, float ba)
{
    float xx1 = fmaxf(p.x, b.x);
    float yy1 = fmaxf(p.y, b.y);
    float xx2 = fminf(p.z, b.z);
    float yy2 = fminf(p.w, b.w);
    float iw  = fmaxf((xx2 - xx1) + 1.0f, 0.0f);
    float ih  = fmaxf((yy2 - yy1) + 1.0f, 0.0f);
    float inter = __fmul_rn(iw, ih);
    float U     = __fadd_rn(__fadd_rn(pa, ba), -inter);
    // exact: 2*inter > U  <=>  fdiv_rn(inter, U) > 0.5   (U > 0 here)
    return __fadd_rn(inter, inter) > U;
}

__global__ void matrix_kernel()
{
    int r    = (blockIdx.x * blockDim.x + threadIdx.x) >> 5;
    int lane = threadIdx.x & 31;
    if (r >= NP) return;

    const float4 pb = reinterpret_cast<const float4*>(g_sbox)[r];
    const float  pa = g_sar[r];

    for (int w = r >> 6; w < NWORD; w++) {
        int c0 = (w << 6) + lane;
        int c1 = c0 + 32;
        float4 b0 = reinterpret_cast<const float4*>(g_sbox)[c0];
        float  a0 = g_sar[c0];
        float4 b1 = reinterpret_cast<const float4*>(g_sbox)[c1];
        float  a1 = g_sar[c1];
        bool s0 = (c0 > r) && sup_test(pb, pa, b0, a0);
        bool s1 = (c1 > r) && sup_test(pb, pa, b1, a1);
        unsigned m0 = __ballot_sync(0xffffffffu, s0);
        unsigned m1 = __ballot_sync(0xffffffffu, s1);
        if (lane == 0)
            g_mask[(size_t)r * NWORD + w] =
                (unsigned long long)m0 | ((unsigned long long)m1 << 32);
    }
}

// ---------------------------------------------------------------------------
// Kernel 4: chunked pick-skip scan with cp.async double-buffered row staging.
//  - alive bitmask (96 u64) in SMEM; dead positions cost nothing (ffsll skip)
//  - chunk c's 64 rows staged to SMEM before the scan touches them; only rows
//    whose alive-bit is set at issue time are loaded (superset of pickable)
//  - per pick: SMEM row ANDN into alive mask by warp 0 (lane-exclusive words)
// Invariant: every alive bit below the scan point is 0, so garbage in
// unloaded/unwritten words can only ANDN already-zero bits.
// ---------------------------------------------------------------------------
__device__ __forceinline__ void cpa16(unsigned long long* dst,
                                      const unsigned long long* src)
{
    unsigned s = (unsigned)__cvta_generic_to_shared(dst);
    asm volatile("cp.async.cg.shared.global [%0], [%1], 16;" :: "r"(s), "l"(src));
}

__global__ void __launch_bounds__(NT_SC, 1) scan_kernel()
{
    extern __shared__ __align__(16) unsigned long long dyn[];
    unsigned long long* buf0  = dyn;                       // 64*NWORD
    unsigned long long* buf1  = dyn + 64 * NWORD;          // 64*NWORD
    unsigned long long* alive = dyn + 2 * 64 * NWORD;      // NWORD
    int* s_picks = (int*)(alive + NWORD);

    const int t    = threadIdx.x;
    const int wid  = t >> 5;
    const int lane = t & 31;

    if (t < NWORD) alive[t] = ~0ull;
    if (t == 0)    *s_picks = 0;
    __syncthreads();

    // ---- prologue: stage chunk 0 (all rows) ----
    {
        unsigned long long* dst = buf0;
        for (int r = wid; r < 64; r += 16) {
            const unsigned long long* src = g_mask + (size_t)r * NWORD;
            for (int u = lane; u < NWORD / 2; u += 32)
                cpa16(dst + r * NWORD + 2 * u, src + 2 * u);
        }
        asm volatile("cp.async.commit_group;");
        asm volatile("cp.async.wait_group 0;");
        __syncthreads();
    }

    for (int c = 0; c < NCHUNK; c++) {
        // ---- issue loads for chunk c+1 (alive-filtered superset) ----
        if (c + 1 < NCHUNK) {
            unsigned long long av = alive[c + 1];
            int w0  = (c + 1) & ~1;             // keep 16B alignment
            int nu  = (NWORD - w0) >> 1;
            unsigned long long* dst = ((c + 1) & 1) ? buf1 : buf0;
            for (int r = wid; r < 64; r += 16) {
                if ((av >> r) & 1ull) {
                    const unsigned long long* src =
                        g_mask + (size_t)((c + 1) * 64 + r) * NWORD + w0;
                    unsigned long long* d = dst + r * NWORD + w0;
                    for (int u = lane; u < nu; u += 32)
                        cpa16(d + 2 * u, src + 2 * u);
                }
            }
            asm volatile("cp.async.commit_group;");
        }

        // ---- warp 0: scan chunk c from the staged buffer ----
        if (wid == 0) {
            const unsigned long long* bufc = (c & 1) ? buf1 : buf0;
            int picks = *s_picks;
            unsigned long long w = alive[c];
            while (w && picks < PAD) {
                int b = __ffsll((long long)w) - 1;
                const unsigned long long* row = bufc + b * NWORD;
                #pragma unroll
                for (int m = 0; m < 3; m++) {
                    int widx = lane + m * 32;
                    unsigned long long rv = row[widx];
                    if (widx == c) rv |= (1ull << b);   // clear own bit too
                    alive[widx] &= ~rv;                 // lane-exclusive RMW
                }
                if (lane == 0) g_pickpos[picks] = c * 64 + b;
                picks++;
                __syncwarp();
                w = alive[c];
            }
            if (lane == 0) *s_picks = picks;
        }

        asm volatile("cp.async.wait_group 0;");
        __syncthreads();
        if (*s_picks >= PAD) break;
    }

    __syncthreads();
    if (t == 0) {
        // exhausted: remaining picks -> last position (a -inf pad => vf=0)
        for (int p = *s_picks; p < PAD; p++) g_pickpos[p] = NP - 1;
    }
}

// ---------------------------------------------------------------------------
// Kernel 5: gather. One block per output slot j; translate sorted pos ->
// original index + validity via the sorted key.
// ---------------------------------------------------------------------------
__global__ void gather_kernel(const float* __restrict__ scores,
                              const float* __restrict__ masks,
                              float* __restrict__ out)
{
    const int j   = blockIdx.x;
    const int pos = g_pickpos[j];
    const unsigned long long key = g_skey[pos];
    const int   i  = NP - 1 - (int)(key & 0x1FFFull);
    const float vf = ((key >> 13) > 0x007FFFFFull) ? 1.0f : 0.0f;
    const int t = threadIdx.x;

    if (t < 4) out[j * 4 + t] = g_pbox[i * 4 + t] * vf;

    const float* srow = scores + (size_t)i * C_CLS;
    float* os = out + PAD * 4 + (size_t)j * C_CLS;
    for (int c = t; c < C_CLS; c += blockDim.x) os[c] = srow[c] * vf;

    const float4* mrow = reinterpret_cast<const float4*>(masks + (size_t)i * MASK_ELEMS);
    float4* om = reinterpret_cast<float4*>(out + PAD * 4 + PAD * C_CLS + (size_t)j * MASK_ELEMS);
    for (int e = t; e < MASK_ELEMS / 4; e += blockDim.x) {
        float4 v = mrow[e];
        v.x *= vf; v.y *= vf; v.z *= vf; v.w *= vf;
        om[e] = v;
    }
}

// ---------------------------------------------------------------------------
extern "C" void kernel_launch(void* const* d_in, const int* in_sizes, int n_in,
                              void* d_out, int out_size)
{
    (void)n_in; (void)out_size;
    const float* metadata  = (const float*)d_in[0];
    const float* deltas    = (const float*)d_in[1];
    const float* proposals = (const float*)d_in[2];
    const float* scores    = (const float*)d_in[3];
    const float* masks     = (const float*)d_in[4];

    int N = in_sizes[2] / 4;
    if (N > NP) N = NP;

    const size_t sort_smem = (size_t)NSORT * sizeof(unsigned long long);   // 64KB
    cudaFuncSetAttribute(sort_kernel, cudaFuncAttributeMaxDynamicSharedMemorySize,
                         (int)sort_smem);
    const size_t scan_smem = (size_t)(2 * 64 * NWORD + NWORD) * sizeof(unsigned long long)
                           + 16;                                           // ~99KB
    cudaFuncSetAttribute(scan_kernel, cudaFuncAttributeMaxDynamicSharedMemorySize,
                         (int)scan_smem);

    // 1) prep: one warp per slot
    {
        const int threads = 256;
        const int blocks  = (NP * 32 + threads - 1) / threads;
        prep_kernel<<<blocks, threads>>>(metadata, deltas, proposals, scores, N);
    }
    // 2) sort
    sort_kernel<<<1, NT_S, sort_smem>>>();
    // 3) suppression matrix: one warp per sorted row
    {
        const int threads = 256;                       // 8 warps/block
        const int blocks  = NP / 8;                    // 768
        matrix_kernel<<<blocks, threads>>>();
    }
    // 4) scan: chunked, one block
    scan_kernel<<<1, NT_SC, scan_smem>>>();
    // 5) gather
    gather_kernel<<<PAD, 512>>>(scores, masks, (float*)d_out);
}

// round 13
// speedup vs baseline: 10.6628x; 1.0142x over previous
#include <cuda_runtime.h>
#include <cstdint>
#include <cstddef>

// ---------------------------------------------------------------------------
// ObjectDetection post-process, sorted-scan NMS formulation:
//   prep   : decode/clip argmax-class box, per-box NMS score, sort key
//   sort   : register-blocked bitonic sort of (score,index) keys
//   matrix : all-pairs suppression bitmask over sorted order (+ diagonal tiles)
//   scan   : diagonal-driven pick-skip scan, exact pick-row gather waves
//   gather : emit boxes/scores/masks
// ---------------------------------------------------------------------------

#define C_CLS      81
#define PAD        300
#define MASK_ELEMS 15876          // 14*14*81

#define NP     6144               // padded proposal slots (>= N=6000), 96*64
#define NWORD  96                 // NP / 64
#define NSORT  8192               // pow2 >= NP for bitonic
#define NT_S   512                // sort threads
#define NT_SC  128                // scan threads (>= NWORD + 32)

__device__ __align__(16) float g_pbox[NP * 4];
__device__ float g_area[NP];
__device__ __align__(16) unsigned long long g_key[NP];     // unsorted keys
__device__ __align__(16) unsigned long long g_skey[NP];    // sorted keys
__device__ __align__(16) float g_sbox[NP * 4];             // boxes, sorted order
__device__ float g_sar[NP];                                // areas, sorted order
__device__ __align__(16) unsigned long long g_mask[(size_t)NP * NWORD]; // 4.7MB
__device__ __align__(16) unsigned long long g_diag[NP];    // row r's word r>>6
__device__ int g_pickpos[PAD];                             // picked sorted positions

__device__ __forceinline__ float neg_inf() { return __int_as_float(0xff800000); }

// ---------------------------------------------------------------------------
// Kernel 1: one warp per proposal. Decode + clip + argmax class + key build.
// (pick-determining arithmetic — unchanged from the passing version)
// ---------------------------------------------------------------------------
__global__ void prep_kernel(const float* __restrict__ metadata,
                            const float* __restrict__ deltas,
                            const float* __restrict__ proposals,
                            const float* __restrict__ scores,
                            int N)
{
    int warp = (blockIdx.x * blockDim.x + threadIdx.x) >> 5;
    int lane = threadIdx.x & 31;
    if (warp >= NP) return;

    if (warp >= N) {            // padding slots: dead entries, -inf keys
        if (lane == 0) {
            reinterpret_cast<float4*>(g_pbox)[warp] = make_float4(0.f, 0.f, 0.f, 0.f);
            g_area[warp] = 0.f;
            g_key[warp] = (0x007FFFFFull << 13) | (unsigned)(NP - 1 - warp);
        }
        return;
    }

    const float* srow = scores + (size_t)warp * C_CLS;
    float bestv = neg_inf();
    int   besti = 0x7fffffff;
    float mx    = neg_inf();
    for (int c = lane; c < C_CLS; c += 32) {
        float v = __ldg(srow + c);
        if (v > bestv || (v == bestv && c < besti)) { bestv = v; besti = c; }
        if (c >= 1) mx = fmaxf(mx, v);
    }
    #pragma unroll
    for (int off = 16; off; off >>= 1) {
        float ov = __shfl_down_sync(0xffffffffu, bestv, off);
        int   oi = __shfl_down_sync(0xffffffffu, besti, off);
        float om = __shfl_down_sync(0xffffffffu, mx,    off);
        if (ov > bestv || (ov == bestv && oi < besti)) { bestv = ov; besti = oi; }
        mx = fmaxf(mx, om);
    }

    if (lane == 0) {
        float H = metadata[0], W = metadata[1], scale = metadata[2];

        float px1 = __fdiv_rn(proposals[warp * 4 + 0], scale);
        float py1 = __fdiv_rn(proposals[warp * 4 + 1], scale);
        float px2 = __fdiv_rn(proposals[warp * 4 + 2], scale);
        float py2 = __fdiv_rn(proposals[warp * 4 + 3], scale);

        float w  = px2 - px1 + 1.0f;
        float h  = py2 - py1 + 1.0f;
        float cx = px1 + 0.5f * w;
        float cy = py1 + 0.5f * h;

        const float* drow = deltas + (size_t)warp * (4 * C_CLS) + (size_t)besti * 4;
        float dx = drow[0], dy = drow[1], dw = drow[2], dh = drow[3];

        float pcx = dx * w + cx;
        float pcy = dy * h + cy;
        float pw  = expf(dw) * w;
        float ph  = expf(dh) * h;

        float x1 = pcx - 0.5f * pw;
        float y1 = pcy - 0.5f * ph;
        float x2 = pcx + 0.5f * pw;
        float y2 = pcy + 0.5f * ph;

        x1 = fminf(fmaxf(x1, 0.f), W - 1.f);
        y1 = fminf(fmaxf(y1, 0.f), H - 1.f);
        x2 = fminf(fmaxf(x2, 0.f), W - 1.f);
        y2 = fminf(fmaxf(y2, 0.f), H - 1.f);

        reinterpret_cast<float4*>(g_pbox)[warp] = make_float4(x1, y1, x2, y2);
        g_area[warp] = (x2 - x1 + 1.f) * (y2 - y1 + 1.f);

        int mb = __float_as_int(mx);
        unsigned mono = (unsigned)mb ^ (unsigned)((mb >> 31) | 0x80000000);
        g_key[warp] = ((unsigned long long)mono << 13) | (unsigned)(NP - 1 - warp);
    }
}

// ---------------------------------------------------------------------------
// Kernel 2: register-blocked bitonic sort (descending). Unchanged (passing).
// ---------------------------------------------------------------------------
#define SWZ(i) ((i) ^ (((i) >> 4) & 15))

__device__ __forceinline__ void cas_d(unsigned long long& a, unsigned long long& b,
                                      bool desc)
{
    unsigned long long mx = (a > b) ? a : b;
    unsigned long long mn = (a > b) ? b : a;
    a = desc ? mx : mn;
    b = desc ? mn : mx;
}

__device__ __forceinline__ void sort16(unsigned long long v[16], bool desc16)
{
    #pragma unroll
    for (int len = 2; len <= 8; len <<= 1) {
        #pragma unroll
        for (int inc = len >> 1; inc >= 1; inc >>= 1) {
            #pragma unroll
            for (int j = 0; j < 16; j++)
                if ((j & inc) == 0)
                    cas_d(v[j], v[j | inc], ((j & len) == 0));
        }
    }
    #pragma unroll
    for (int inc = 8; inc >= 1; inc >>= 1) {
        #pragma unroll
        for (int j = 0; j < 16; j++)
            if ((j & inc) == 0)
                cas_d(v[j], v[j | inc], desc16);
    }
}

__device__ __forceinline__ void merge16(unsigned long long v[16], bool desc)
{
    #pragma unroll
    for (int inc = 8; inc >= 1; inc >>= 1) {
        #pragma unroll
        for (int j = 0; j < 16; j++)
            if ((j & inc) == 0)
                cas_d(v[j], v[j | inc], desc);
    }
}

__global__ void __launch_bounds__(NT_S, 1) sort_kernel()
{
    extern __shared__ __align__(16) unsigned long long s[];
    const int t    = threadIdx.x;
    const int base = t * 16;

    unsigned long long v[16];
    #pragma unroll
    for (int j = 0; j < 16; j++) {
        int i = base + j;
        v[j] = (i < NP) ? g_key[i] : 0ull;       // fillers sort last (desc)
    }
    sort16(v, ((base & 16) == 0));
    #pragma unroll
    for (int j = 0; j < 16; j++) s[SWZ(base + j)] = v[j];
    __syncthreads();

    for (int len = 32; len <= NSORT; len <<= 1) {
        for (int inc = len >> 1; inc >= 16; inc >>= 1) {
            for (int ii = t; ii < NSORT / 2; ii += NT_S) {
                int low = ii & (inc - 1);
                int i   = ((ii ^ low) << 1) | low;
                int j   = i + inc;
                unsigned long long a = s[SWZ(i)], b = s[SWZ(j)];
                bool up = ((i & len) == 0);
                bool sw_ = up ? (a < b) : (a > b);   // descending network
                if (sw_) { s[SWZ(i)] = b; s[SWZ(j)] = a; }
            }
            __syncthreads();
        }
        #pragma unroll
        for (int j = 0; j < 16; j++) v[j] = s[SWZ(base + j)];
        merge16(v, ((base & len) == 0));
        #pragma unroll
        for (int j = 0; j < 16; j++) s[SWZ(base + j)] = v[j];
        __syncthreads();
    }

    for (int pos = t; pos < NP; pos += NT_S) {
        unsigned long long key = s[SWZ(pos)];
        int k = NP - 1 - (int)(key & 0x1FFFull);
        g_skey[pos] = key;
        reinterpret_cast<float4*>(g_sbox)[pos] =
            reinterpret_cast<const float4*>(g_pbox)[k];
        g_sar[pos] = g_area[k];
    }
}

// ---------------------------------------------------------------------------
// Kernel 3: suppression matrix over sorted order. One warp per row r;
// word w (>= r/64) packs [IoU(r,c) > 0.5] for c in [64w,64w+64), c > r.
// Also emits the diagonal word (w == r>>6) contiguously into g_diag.
// ---------------------------------------------------------------------------
__device__ __forceinline__ bool sup_test(float4 p, float pa, float4 b, float ba)
{
    float xx1 = fmaxf(p.x, b.x);
    float yy1 = fmaxf(p.y, b.y);
    float xx2 = fminf(p.z, b.z);
    float yy2 = fminf(p.w, b.w);
    float iw  = fmaxf((xx2 - xx1) + 1.0f, 0.0f);
    float ih  = fmaxf((yy2 - yy1) + 1.0f, 0.0f);
    float inter = __fmul_rn(iw, ih);
    float U     = __fadd_rn(__fadd_rn(pa, ba), -inter);
    // exact: 2*inter > U  <=>  fdiv_rn(inter, U) > 0.5   (U > 0 here)
    return __fadd_rn(inter, inter) > U;
}

__global__ void matrix_kernel()
{
    int r    = (blockIdx.x * blockDim.x + threadIdx.x) >> 5;
    int lane = threadIdx.x & 31;
    if (r >= NP) return;

    const float4 pb = reinterpret_cast<const float4*>(g_sbox)[r];
    const float  pa = g_sar[r];
    const int    wd = r >> 6;

    for (int w = wd; w < NWORD; w++) {
        int c0 = (w << 6) + lane;
        int c1 = c0 + 32;
        float4 b0 = reinterpret_cast<const float4*>(g_sbox)[c0];
        float  a0 = g_sar[c0];
        float4 b1 = reinterpret_cast<const float4*>(g_sbox)[c1];
        float  a1 = g_sar[c1];
        bool s0 = (c0 > r) && sup_test(pb, pa, b0, a0);
        bool s1 = (c1 > r) && sup_test(pb, pa, b1, a1);
        unsigned m0 = __ballot_sync(0xffffffffu, s0);
        unsigned m1 = __ballot_sync(0xffffffffu, s1);
        if (lane == 0) {
            unsigned long long word =
                (unsigned long long)m0 | ((unsigned long long)m1 << 32);
            g_mask[(size_t)r * NWORD + w] = word;
            if (w == wd) g_diag[r] = word;     // diagonal tile, contiguous
        }
    }
}

// ---------------------------------------------------------------------------
// Kernel 4: diagonal-driven pick-skip scan, ONE block of 128 threads.
//  - all 96 diagonal tiles (48KB) staged to SMEM once (cp.async)
//  - within-chunk pick chain uses ONLY the smem diagonal (no global loads)
//  - per chunk, cross-chunk suppression applied exactly for the k actual
//    picks: thread j owns alive word c+1+j and gathers that column from the
//    k pick rows (independent loads -> one L2 latency wave), then one write.
//  - every nonzero alive word yields >=1 pick, so waves <= min(96, PAD).
// ---------------------------------------------------------------------------
__device__ __forceinline__ void cpa16(unsigned long long* dst,
                                      const unsigned long long* src)
{
    unsigned s = (unsigned)__cvta_generic_to_shared(dst);
    asm volatile("cp.async.cg.shared.global [%0], [%1], 16;" :: "r"(s), "l"(src));
}

__global__ void __launch_bounds__(NT_SC, 1) scan_kernel()
{
    extern __shared__ __align__(16) unsigned long long dyn[];
    unsigned long long* diag  = dyn;               // NP u64 = 48KB
    unsigned long long* alive = dyn + NP;          // NWORD u64
    int* s_rows = (int*)(alive + NWORD);           // up to 64 pick rows
    int* s_meta = s_rows + 64;                     // [0]=k, [1]=total picks

    const int t = threadIdx.x;

    // stage all diagonal tiles
    for (int u = t; u < NP / 2; u += NT_SC)
        cpa16(diag + 2 * u, g_diag + 2 * u);
    asm volatile("cp.async.commit_group;");

    if (t < NWORD) alive[t] = ~0ull;
    if (t == 0) { s_meta[0] = 0; s_meta[1] = 0; }
    asm volatile("cp.async.wait_group 0;");
    __syncthreads();

    for (int c = 0; c < NWORD; c++) {
        unsigned long long w0 = alive[c];
        if (w0 == 0ull) continue;

        // ---- thread 0: within-chunk pick chain (smem diagonal only) ----
        if (t == 0) {
            unsigned long long w = w0;
            int pk = s_meta[1];
            int k  = 0;
            while (w && pk < PAD) {
                int b = __ffsll((long long)w) - 1;
                int R = (c << 6) + b;
                g_pickpos[pk++] = R;
                s_rows[k++] = R;
                w &= ~diag[R];             // suppress within-word (bits > b)
                w &= ~(1ull << b);         // clear own bit
            }
            s_meta[0] = k;
            s_meta[1] = pk;
        }
        __syncthreads();

        const int k = s_meta[0];
        // ---- apply wave: thread j owns alive word c+1+j ----
        int wj = c + 1 + t;
        if (wj < NWORD && k > 0) {
            unsigned long long acc = alive[wj];
            for (int p = 0; p < k; p++)
                acc &= ~g_mask[(size_t)s_rows[p] * NWORD + wj];
            alive[wj] = acc;
        }
        __syncthreads();
        if (s_meta[1] >= PAD) break;
    }

    if (t == 0) {
        // exhausted: remaining picks -> last position (a -inf pad => vf=0)
        for (int p = s_meta[1]; p < PAD; p++) g_pickpos[p] = NP - 1;
    }
}

// ---------------------------------------------------------------------------
// Kernel 5: gather. Grid (PAD, 4): slice y of the mask row per block;
// slice 0 also writes boxes + scores.
// ---------------------------------------------------------------------------
__global__ void gather_kernel(const float* __restrict__ scores,
                              const float* __restrict__ masks,
                              float* __restrict__ out)
{
    const int j   = blockIdx.x;
    const int sl  = blockIdx.y;
    const int pos = g_pickpos[j];
    const unsigned long long key = g_skey[pos];
    const int   i  = NP - 1 - (int)(key & 0x1FFFull);
    const float vf = ((key >> 13) > 0x007FFFFFull) ? 1.0f : 0.0f;
    const int t = threadIdx.x;

    if (sl == 0) {
        if (t < 4) out[j * 4 + t] = g_pbox[i * 4 + t] * vf;
        const float* srow = scores + (size_t)i * C_CLS;
        float* os = out + PAD * 4 + (size_t)j * C_CLS;
        for (int c = t; c < C_CLS; c += blockDim.x) os[c] = srow[c] * vf;
    }

    const int NM4   = MASK_ELEMS / 4;            // 3969
    const int per   = (NM4 + 3) / 4;             // 993
    const int e0    = sl * per;
    const int e1    = (e0 + per < NM4) ? (e0 + per) : NM4;

    const float4* mrow = reinterpret_cast<const float4*>(masks + (size_t)i * MASK_ELEMS);
    float4* om = reinterpret_cast<float4*>(out + PAD * 4 + PAD * C_CLS + (size_t)j * MASK_ELEMS);
    for (int e = e0 + t; e < e1; e += blockDim.x) {
        float4 v = mrow[e];
        v.x *= vf; v.y *= vf; v.z *= vf; v.w *= vf;
        om[e] = v;
    }
}

// ---------------------------------------------------------------------------
extern "C" void kernel_launch(void* const* d_in, const int* in_sizes, int n_in,
                              void* d_out, int out_size)
{
    (void)n_in; (void)out_size;
    const float* metadata  = (const float*)d_in[0];
    const float* deltas    = (const float*)d_in[1];
    const float* proposals = (const float*)d_in[2];
    const float* scores    = (const float*)d_in[3];
    const float* masks     = (const float*)d_in[4];

    int N = in_sizes[2] / 4;
    if (N > NP) N = NP;

    const size_t sort_smem = (size_t)NSORT * sizeof(unsigned long long);   // 64KB
    cudaFuncSetAttribute(sort_kernel, cudaFuncAttributeMaxDynamicSharedMemorySize,
                         (int)sort_smem);
    const size_t scan_smem = (size_t)(NP + NWORD) * sizeof(unsigned long long)
                           + 66 * sizeof(int);                             // ~49.3KB
    cudaFuncSetAttribute(scan_kernel, cudaFuncAttributeMaxDynamicSharedMemorySize,
                         (int)scan_smem);

    // 1) prep: one warp per slot
    {
        const int threads = 256;
        const int blocks  = (NP * 32 + threads - 1) / threads;
        prep_kernel<<<blocks, threads>>>(metadata, deltas, proposals, scores, N);
    }
    // 2) sort
    sort_kernel<<<1, NT_S, sort_smem>>>();
    // 3) suppression matrix: one warp per sorted row
    {
        const int threads = 256;                       // 8 warps/block
        const int blocks  = NP / 8;                    // 768
        matrix_kernel<<<blocks, threads>>>();
    }
    // 4) scan: one block, diagonal-driven
    scan_kernel<<<1, NT_SC, scan_smem>>>();
    // 5) gather: mask rows split over 4 slices
    {
        dim3 grid(PAD, 4);
        gather_kernel<<<grid, 256>>>(scores, masks, (float*)d_out);
    }
}